// round 11
// baseline (speedup 1.0000x reference)
#include <cuda_runtime.h>
#include <cuda_fp16.h>
#include <math.h>

#define N_NODES 100000
#define N_EDGES 1250000
#define D 64
#define N_LAYERS 4

// ---- fused layer kernel config ----
#define TPB 256                       // 8 warps, 1 M-tile (16 nodes) each
#define NPB 128                       // nodes per block
#define A_PITCH 136                   // halves; 272B row stride -> conflict-free LDSM
#define W_PITCH 72                    // halves; 144B row stride -> conflict-free LDSM
#define SA_HALVES (NPB * A_PITCH)     // 17408
#define SW_HALVES (128 * W_PITCH)     // 9216
#define SMEM_BYTES ((SA_HALVES + SW_HALVES) * 2 + D * 4)

// ---- scan config ----
#define SBLK 1024
#define NSB ((N_NODES + SBLK - 1) / SBLK)   // 98

// ---------------- scratch (static device globals) ---------------------------
__device__ __half g_x16[N_NODES * D];
__device__ __half g_h16a[N_NODES * D];
__device__ __half g_h16b[N_NODES * D];
__device__ int    g_counts[N_NODES];
__device__ int    g_rowptr[N_NODES + 1];
__device__ int    g_cursor[N_NODES];
__device__ int    g_csr[N_EDGES];
__device__ int    g_bsums[NSB];
__device__ int    g_is64;

// ---------------- mma helpers ------------------------------------------------
__device__ __forceinline__ unsigned s2u(const void* p) {
    return (unsigned)__cvta_generic_to_shared(p);
}
__device__ __forceinline__ void ldmx4(unsigned& a0, unsigned& a1,
                                      unsigned& a2, unsigned& a3, unsigned addr) {
    asm volatile("ldmatrix.sync.aligned.m8n8.x4.shared.b16 {%0,%1,%2,%3}, [%4];"
                 : "=r"(a0), "=r"(a1), "=r"(a2), "=r"(a3) : "r"(addr));
}
__device__ __forceinline__ void ldmx2t(unsigned& b0, unsigned& b1, unsigned addr) {
    asm volatile("ldmatrix.sync.aligned.m8n8.x2.trans.shared.b16 {%0,%1}, [%2];"
                 : "=r"(b0), "=r"(b1) : "r"(addr));
}
__device__ __forceinline__ void mma16816(float* c, unsigned a0, unsigned a1,
                                         unsigned a2, unsigned a3,
                                         unsigned b0, unsigned b1) {
    asm volatile(
        "mma.sync.aligned.m16n8k16.row.col.f32.f16.f16.f32 "
        "{%0,%1,%2,%3}, {%4,%5,%6,%7}, {%8,%9}, {%0,%1,%2,%3};"
        : "+f"(c[0]), "+f"(c[1]), "+f"(c[2]), "+f"(c[3])
        : "r"(a0), "r"(a1), "r"(a2), "r"(a3), "r"(b0), "r"(b1));
}

// ---------------- init: zero counts + dtype detect + x->fp16 -----------------
__global__ void init_cvt_kernel(const void* __restrict__ edge_raw,
                                const float* __restrict__ x) {
    int i = blockIdx.x * blockDim.x + threadIdx.x;
    if (i < N_NODES * D / 2) {
        float2 v = ((const float2*)x)[i];
        ((__half2*)g_x16)[i] = __floats2half2_rn(v.x, v.y);
    }
    if (i < N_NODES) g_counts[i] = 0;
    if (i == 0) {
        const long long* e64 = (const long long*)edge_raw;
        int ok64 = 1;
        #pragma unroll 8
        for (int t = 0; t < 64; t++) {
            long long v = e64[t];
            if (v < 0 || v >= N_NODES) ok64 = 0;
        }
        g_is64 = ok64;
    }
}

// ---------------- CSR build (2 edges per thread) -----------------------------
__global__ void histogram_kernel(const void* __restrict__ edge_raw) {
    int p = blockIdx.x * blockDim.x + threadIdx.x;      // edge pair index
    int e = p * 2;
    if (e >= N_EDGES) return;
    int d0, d1;
    if (g_is64) {
        longlong2 v = ((const longlong2*)edge_raw)[N_EDGES / 2 + p];
        d0 = (int)v.x; d1 = (int)v.y;
    } else {
        int2 v = ((const int2*)edge_raw)[N_EDGES / 2 + p];
        d0 = v.x; d1 = v.y;
    }
    if (d0 >= 0 && d0 < N_NODES) atomicAdd(&g_counts[d0], 1);
    if (e + 1 < N_EDGES && d1 >= 0 && d1 < N_NODES) atomicAdd(&g_counts[d1], 1);
}

__global__ __launch_bounds__(SBLK) void scan1_kernel() {
    __shared__ int wsum[32];
    int tid = threadIdx.x, lane = tid & 31, w = tid >> 5;
    int i = blockIdx.x * SBLK + tid;
    int v = (i < N_NODES) ? g_counts[i] : 0;
    int x = v;
    #pragma unroll
    for (int off = 1; off < 32; off <<= 1) {
        int y = __shfl_up_sync(0xffffffffu, x, off);
        if (lane >= off) x += y;
    }
    if (lane == 31) wsum[w] = x;
    __syncthreads();
    if (w == 0) {
        int s = wsum[lane];
        #pragma unroll
        for (int off = 1; off < 32; off <<= 1) {
            int y = __shfl_up_sync(0xffffffffu, s, off);
            if (lane >= off) s += y;
        }
        wsum[lane] = s;
    }
    __syncthreads();
    int incl = x + ((w > 0) ? wsum[w - 1] : 0);
    if (i < N_NODES) g_rowptr[i] = incl - v;
    if (tid == SBLK - 1) g_bsums[blockIdx.x] = incl;
}

__global__ __launch_bounds__(SBLK) void scan3_kernel() {
    __shared__ int sExcl[NSB];
    __shared__ int sTot;
    int tid = threadIdx.x;
    if (tid < 32) {
        int carry = 0;
        #pragma unroll
        for (int base = 0; base < NSB; base += 32) {
            int idx = base + tid;
            int v = (idx < NSB) ? g_bsums[idx] : 0;
            int x = v;
            #pragma unroll
            for (int off = 1; off < 32; off <<= 1) {
                int y = __shfl_up_sync(0xffffffffu, x, off);
                if (tid >= off) x += y;
            }
            if (idx < NSB) sExcl[idx] = carry + x - v;
            carry += __shfl_sync(0xffffffffu, x, 31);
        }
        if (tid == 0) sTot = carry;
    }
    __syncthreads();
    int i = blockIdx.x * SBLK + tid;
    if (i < N_NODES) {
        int r = g_rowptr[i] + sExcl[blockIdx.x];
        g_rowptr[i] = r;
        g_cursor[i] = r;
    }
    if (blockIdx.x == 0 && tid == 0) g_rowptr[N_NODES] = sTot;
}

__global__ void scatter_kernel(const void* __restrict__ edge_raw) {
    int p = blockIdx.x * blockDim.x + threadIdx.x;      // edge pair index
    int e = p * 2;
    if (e >= N_EDGES) return;
    int s0, s1, d0, d1;
    if (g_is64) {
        longlong2 sv = ((const longlong2*)edge_raw)[p];
        longlong2 dv = ((const longlong2*)edge_raw)[N_EDGES / 2 + p];
        s0 = (int)sv.x; s1 = (int)sv.y; d0 = (int)dv.x; d1 = (int)dv.y;
    } else {
        int2 sv = ((const int2*)edge_raw)[p];
        int2 dv = ((const int2*)edge_raw)[N_EDGES / 2 + p];
        s0 = sv.x; s1 = sv.y; d0 = dv.x; d1 = dv.y;
    }
    if (s0 >= 0 && s0 < N_NODES && d0 >= 0 && d0 < N_NODES) {
        int pos = atomicAdd(&g_cursor[d0], 1);
        if (pos >= 0 && pos < N_EDGES) g_csr[pos] = s0;
    }
    if (e + 1 < N_EDGES && s1 >= 0 && s1 < N_NODES && d1 >= 0 && d1 < N_NODES) {
        int pos = atomicAdd(&g_cursor[d1], 1);
        if (pos >= 0 && pos < N_EDGES) g_csr[pos] = s1;
    }
}

// ---------------- fused layer (gather + HMMA gemm) ---------------------------
// Per block: gather 128 nodes' max-pool agg + self rows straight into sA
// ([0:64]=agg, [64:128]=h), then C[128x64] = A @ [Wl;Wr] + bias, relu.
#define GMAX2(v) do { \
    m0 = __hmax2(m0, *(__half2*)&(v).x); m1 = __hmax2(m1, *(__half2*)&(v).y); \
    m2 = __hmax2(m2, *(__half2*)&(v).z); m3 = __hmax2(m3, *(__half2*)&(v).w); } while (0)

template <int OUT16>
__global__ __launch_bounds__(TPB) void layer_kernel(
    const __half* __restrict__ h_in, void* __restrict__ outp,
    const float* __restrict__ Wl, const float* __restrict__ bl,
    const float* __restrict__ Wr, int layer)
{
    extern __shared__ __half smem16[];
    __half* sA = smem16;                  // [128][A_PITCH]: cols 0-63 agg, 64-127 h
    __half* sW = smem16 + SA_HALVES;      // [128][W_PITCH]: rows 0-63 Wl, 64-127 Wr
    float*  sB = (float*)(smem16 + SA_HALVES + SW_HALVES);

    int tid = threadIdx.x;
    int blockBase = blockIdx.x * NPB;

    // stage W (fp32 -> fp16) + bias
    {
        const float4* wl4 = (const float4*)(Wl + layer * D * D);
        const float4* wr4 = (const float4*)(Wr + layer * D * D);
        #pragma unroll
        for (int i = tid; i < 2048; i += TPB) {
            int row = i >> 4, c = i & 15;
            float4 v = (row < 64) ? wl4[row * 16 + c] : wr4[(row - 64) * 16 + c];
            __half2 h0 = __floats2half2_rn(v.x, v.y);
            __half2 h1 = __floats2half2_rn(v.z, v.w);
            uint2 u;
            u.x = *(unsigned*)&h0; u.y = *(unsigned*)&h1;
            *(uint2*)(sW + row * W_PITCH + c * 4) = u;
        }
        if (tid < D) sB[tid] = bl[layer * D + tid];
    }

    int warp = tid >> 5, lane = tid & 31;
    int sub = lane >> 3, dl = lane & 7;

    // gather phase: warp w fills sA rows [16w, 16w+16); 4-node subgroups x 4 rounds
    #pragma unroll 1
    for (int r = 0; r < 4; r++) {
        int row = warp * 16 + r * 4 + sub;
        int node = blockBase + row;
        bool valid = (node < N_NODES);
        int start = 0, end = 0;
        if (valid) { start = g_rowptr[node]; end = g_rowptr[node + 1]; }

        const __half neginf = __ushort_as_half((unsigned short)0xFC00);
        __half2 m0 = __half2half2(neginf), m1 = m0, m2 = m0, m3 = m0;

        int j = start;
        #pragma unroll 1
        for (; j + 4 <= end; j += 4) {
            int s0 = g_csr[j],     s1 = g_csr[j + 1];
            int s2 = g_csr[j + 2], s3 = g_csr[j + 3];
            uint4 v0 = *(const uint4*)(h_in + (size_t)s0 * D + dl * 8);
            uint4 v1 = *(const uint4*)(h_in + (size_t)s1 * D + dl * 8);
            uint4 v2 = *(const uint4*)(h_in + (size_t)s2 * D + dl * 8);
            uint4 v3 = *(const uint4*)(h_in + (size_t)s3 * D + dl * 8);
            GMAX2(v0); GMAX2(v1); GMAX2(v2); GMAX2(v3);
        }
        if (j + 2 <= end) {
            int s0 = g_csr[j], s1 = g_csr[j + 1];
            uint4 v0 = *(const uint4*)(h_in + (size_t)s0 * D + dl * 8);
            uint4 v1 = *(const uint4*)(h_in + (size_t)s1 * D + dl * 8);
            GMAX2(v0); GMAX2(v1);
            j += 2;
        }
        if (j < end) {
            int s0 = g_csr[j];
            uint4 v0 = *(const uint4*)(h_in + (size_t)s0 * D + dl * 8);
            GMAX2(v0);
        }
        if (start == end) {
            __half2 z = __half2half2(__ushort_as_half((unsigned short)0));
            m0 = z; m1 = z; m2 = z; m3 = z;
        }
        uint4 aggv;
        aggv.x = *(unsigned*)&m0; aggv.y = *(unsigned*)&m1;
        aggv.z = *(unsigned*)&m2; aggv.w = *(unsigned*)&m3;
        uint4 selfv = make_uint4(0, 0, 0, 0);
        if (valid) selfv = *(const uint4*)(h_in + (size_t)node * D + dl * 8);
        *(uint4*)(sA + row * A_PITCH + dl * 8)      = aggv;
        *(uint4*)(sA + row * A_PITCH + 64 + dl * 8) = selfv;
    }
    __syncthreads();

    // mma phase
    float acc[8][4];
    #pragma unroll
    for (int n = 0; n < 8; n++) {
        acc[n][0] = 0.f; acc[n][1] = 0.f; acc[n][2] = 0.f; acc[n][3] = 0.f;
    }
    unsigned aBase = s2u(sA) + ((warp * 16 + (lane & 15)) * A_PITCH + (lane >> 4) * 8) * 2;
    unsigned bBase = s2u(sW) + ((lane & 15) * W_PITCH) * 2;

    #pragma unroll
    for (int kk = 0; kk < 8; kk++) {
        unsigned a0, a1, a2, a3;
        ldmx4(a0, a1, a2, a3, aBase + kk * 16 * 2);
        unsigned brow = bBase + kk * 16 * W_PITCH * 2;
        #pragma unroll
        for (int n = 0; n < 8; n++) {
            unsigned b0, b1;
            ldmx2t(b0, b1, brow + n * 8 * 2);
            mma16816(acc[n], a0, a1, a2, a3, b0, b1);
        }
    }

    // epilogue: bias + relu
    int g = lane >> 2, t = lane & 3;
    if (OUT16) {
        __syncthreads();                  // reuse sA as sC
        #pragma unroll
        for (int n = 0; n < 8; n++) {
            int col = n * 8 + t * 2;
            float bx = sB[col], by = sB[col + 1];
            __half2 h01 = __floats2half2_rn(fmaxf(acc[n][0] + bx, 0.f),
                                            fmaxf(acc[n][1] + by, 0.f));
            __half2 h23 = __floats2half2_rn(fmaxf(acc[n][2] + bx, 0.f),
                                            fmaxf(acc[n][3] + by, 0.f));
            *(__half2*)(sA + (warp * 16 + g)     * A_PITCH + col) = h01;
            *(__half2*)(sA + (warp * 16 + g + 8) * A_PITCH + col) = h23;
        }
        __syncthreads();
        __half* o16 = (__half*)outp;
        #pragma unroll
        for (int i = tid; i < NPB * 8; i += TPB) {
            int row = i >> 3, c = i & 7;
            int node = blockBase + row;
            if (node < N_NODES)
                *(uint4*)(o16 + (size_t)node * D + c * 8) =
                    *(uint4*)(sA + row * A_PITCH + c * 8);
        }
    } else {
        float* o32 = (float*)outp;
        int row0 = blockBase + warp * 16 + g;
        int row1 = row0 + 8;
        #pragma unroll
        for (int n = 0; n < 8; n++) {
            int col = n * 8 + t * 2;
            float bx = sB[col], by = sB[col + 1];
            if (row0 < N_NODES) {
                float2 v = make_float2(fmaxf(acc[n][0] + bx, 0.f),
                                       fmaxf(acc[n][1] + by, 0.f));
                *(float2*)(o32 + (size_t)row0 * D + col) = v;
            }
            if (row1 < N_NODES) {
                float2 v = make_float2(fmaxf(acc[n][2] + bx, 0.f),
                                       fmaxf(acc[n][3] + by, 0.f));
                *(float2*)(o32 + (size_t)row1 * D + col) = v;
            }
        }
    }
}

// ---------------- launch -----------------------------------------------------
extern "C" void kernel_launch(void* const* d_in, const int* in_sizes, int n_in,
                              void* d_out, int out_size) {
    const float* x  = nullptr;
    const void*  edge = nullptr;
    const float* Wl = nullptr;
    const float* Wr = nullptr;
    const float* bl = nullptr;
    for (int i = 0; i < n_in; i++) {
        int sz = in_sizes[i];
        if (sz == N_NODES * D)            x    = (const float*)d_in[i];
        else if (sz == 2 * N_EDGES)       edge = d_in[i];
        else if (sz == N_LAYERS * D * D) { if (!Wl) Wl = (const float*)d_in[i];
                                           else     Wr = (const float*)d_in[i]; }
        else if (sz == N_LAYERS * D)      bl   = (const float*)d_in[i];
    }
    float* out = (float*)d_out;

    static int smem_set = 0;
    if (!smem_set) {
        cudaFuncSetAttribute(layer_kernel<1>,
                             cudaFuncAttributeMaxDynamicSharedMemorySize, SMEM_BYTES);
        cudaFuncSetAttribute(layer_kernel<0>,
                             cudaFuncAttributeMaxDynamicSharedMemorySize, SMEM_BYTES);
        smem_set = 1;
    }

    init_cvt_kernel<<<(N_NODES * D / 2 + 255) / 256, 256>>>(edge, x);
    histogram_kernel<<<(N_EDGES / 2 + 255) / 256, 256>>>(edge);
    scan1_kernel<<<NSB, SBLK>>>();
    scan3_kernel<<<NSB, SBLK>>>();
    scatter_kernel<<<(N_EDGES / 2 + 255) / 256, 256>>>(edge);

    int mblocks = (N_NODES + NPB - 1) / NPB;

    __half* x16 = nullptr; __half* h16a = nullptr; __half* h16b = nullptr;
    cudaGetSymbolAddress((void**)&x16, g_x16);
    cudaGetSymbolAddress((void**)&h16a, g_h16a);
    cudaGetSymbolAddress((void**)&h16b, g_h16b);

    layer_kernel<1><<<mblocks, TPB, SMEM_BYTES>>>(x16,  h16a, Wl, bl, Wr, 0);
    layer_kernel<1><<<mblocks, TPB, SMEM_BYTES>>>(h16a, h16b, Wl, bl, Wr, 1);
    layer_kernel<1><<<mblocks, TPB, SMEM_BYTES>>>(h16b, h16a, Wl, bl, Wr, 2);
    layer_kernel<0><<<mblocks, TPB, SMEM_BYTES>>>(h16a, out,  Wl, bl, Wr, 3);
}

// round 12
// speedup vs baseline: 1.1101x; 1.1101x over previous
#include <cuda_runtime.h>
#include <cuda_fp16.h>
#include <math.h>

#define N_NODES 100000
#define N_EDGES 1250000
#define D 64
#define N_LAYERS 4

// ---- gemm kernel config ----
#define TPB 256                       // 8 warps, 1 M-tile (16 nodes) each
#define NPB 128                       // nodes per block
#define A_PITCH 136                   // halves; 272B row stride -> conflict-free LDSM
#define W_PITCH 72                    // halves; 144B row stride -> conflict-free LDSM
#define SA_HALVES (NPB * A_PITCH)     // 17408
#define SW_HALVES (128 * W_PITCH)     // 9216
#define SMEM_BYTES ((SA_HALVES + SW_HALVES) * 2 + D * 4)

// ---- gather kernel config ----
#define GTPB 256
#define GNPB 32

// ---- scan config ----
#define SBLK 1024
#define NSB ((N_NODES + SBLK - 1) / SBLK)   // 98 blocks <= 148 SMs: lookback safe

// ---------------- scratch (static device globals) ---------------------------
__device__ __half g_x16[N_NODES * D];
__device__ __half g_h16a[N_NODES * D];
__device__ __half g_h16b[N_NODES * D];
__device__ __half g_agg16[N_NODES * D];
__device__ int    g_counts[N_NODES];
__device__ int    g_rowptr[N_NODES + 1];
__device__ int    g_cursor[N_NODES];
__device__ int    g_csr[N_EDGES];
__device__ unsigned long long g_bstat[NSB];   // lookback: flag<<32 | value
__device__ int    g_is64;

// ---------------- mma helpers ------------------------------------------------
__device__ __forceinline__ unsigned s2u(const void* p) {
    return (unsigned)__cvta_generic_to_shared(p);
}
__device__ __forceinline__ void ldmx4(unsigned& a0, unsigned& a1,
                                      unsigned& a2, unsigned& a3, unsigned addr) {
    asm volatile("ldmatrix.sync.aligned.m8n8.x4.shared.b16 {%0,%1,%2,%3}, [%4];"
                 : "=r"(a0), "=r"(a1), "=r"(a2), "=r"(a3) : "r"(addr));
}
__device__ __forceinline__ void ldmx2t(unsigned& b0, unsigned& b1, unsigned addr) {
    asm volatile("ldmatrix.sync.aligned.m8n8.x2.trans.shared.b16 {%0,%1}, [%2];"
                 : "=r"(b0), "=r"(b1) : "r"(addr));
}
__device__ __forceinline__ void mma16816(float* c, unsigned a0, unsigned a1,
                                         unsigned a2, unsigned a3,
                                         unsigned b0, unsigned b1) {
    asm volatile(
        "mma.sync.aligned.m16n8k16.row.col.f32.f16.f16.f32 "
        "{%0,%1,%2,%3}, {%4,%5,%6,%7}, {%8,%9}, {%0,%1,%2,%3};"
        : "+f"(c[0]), "+f"(c[1]), "+f"(c[2]), "+f"(c[3])
        : "r"(a0), "r"(a1), "r"(a2), "r"(a3), "r"(b0), "r"(b1));
}

// ---------------- init: zero counts/status + dtype detect + x->fp16 ----------
__global__ void init_cvt_kernel(const void* __restrict__ edge_raw,
                                const float* __restrict__ x) {
    int i = blockIdx.x * blockDim.x + threadIdx.x;
    if (i < N_NODES * D / 2) {
        float2 v = ((const float2*)x)[i];
        ((__half2*)g_x16)[i] = __floats2half2_rn(v.x, v.y);
    }
    if (i < N_NODES) g_counts[i] = 0;
    if (i < NSB) g_bstat[i] = 0ull;
    if (i == 0) {
        const long long* e64 = (const long long*)edge_raw;
        int ok64 = 1;
        #pragma unroll 8
        for (int t = 0; t < 64; t++) {
            long long v = e64[t];
            if (v < 0 || v >= N_NODES) ok64 = 0;
        }
        g_is64 = ok64;
    }
}

// ---------------- CSR build (2 edges per thread) -----------------------------
__global__ void histogram_kernel(const void* __restrict__ edge_raw) {
    int p = blockIdx.x * blockDim.x + threadIdx.x;      // edge pair index
    int e = p * 2;
    if (e >= N_EDGES) return;
    int d0, d1;
    if (g_is64) {
        longlong2 v = ((const longlong2*)edge_raw)[N_EDGES / 2 + p];
        d0 = (int)v.x; d1 = (int)v.y;
    } else {
        int2 v = ((const int2*)edge_raw)[N_EDGES / 2 + p];
        d0 = v.x; d1 = v.y;
    }
    if (d0 >= 0 && d0 < N_NODES) atomicAdd(&g_counts[d0], 1);
    if (e + 1 < N_EDGES && d1 >= 0 && d1 < N_NODES) atomicAdd(&g_counts[d1], 1);
}

// single-pass decoupled-lookback exclusive scan: counts -> rowptr (+cursor)
__global__ __launch_bounds__(SBLK) void scan_kernel() {
    __shared__ int wsum[32];
    __shared__ int sPrefix;
    int tid = threadIdx.x, lane = tid & 31, w = tid >> 5;
    int bid = blockIdx.x;
    int i = bid * SBLK + tid;
    int v = (i < N_NODES) ? g_counts[i] : 0;

    int x = v;
    #pragma unroll
    for (int off = 1; off < 32; off <<= 1) {
        int y = __shfl_up_sync(0xffffffffu, x, off);
        if (lane >= off) x += y;
    }
    if (lane == 31) wsum[w] = x;
    __syncthreads();
    if (w == 0) {
        int s = wsum[lane];
        #pragma unroll
        for (int off = 1; off < 32; off <<= 1) {
            int y = __shfl_up_sync(0xffffffffu, s, off);
            if (lane >= off) s += y;
        }
        wsum[lane] = s;
    }
    __syncthreads();
    int incl = x + ((w > 0) ? wsum[w - 1] : 0);
    int total = wsum[31];                     // block aggregate

    if (tid == 0) {
        if (bid == 0) {
            sPrefix = 0;
            atomicExch(&g_bstat[0], (2ull << 32) | (unsigned)total);
        } else {
            // publish aggregate, then look back
            atomicExch(&g_bstat[bid], (1ull << 32) | (unsigned)total);
            int sum = 0;
            int p = bid - 1;
            while (true) {
                unsigned long long s = atomicAdd(&g_bstat[p], 0ull);
                unsigned flag = (unsigned)(s >> 32);
                if (flag == 0u) continue;     // predecessor not ready; spin
                sum += (int)(unsigned)s;
                if (flag == 2u) break;        // hit an inclusive prefix
                p--;
            }
            sPrefix = sum;
            atomicExch(&g_bstat[bid], (2ull << 32) | (unsigned)(sum + total));
        }
    }
    __syncthreads();
    int base = sPrefix;
    if (i < N_NODES) {
        int r = base + incl - v;
        g_rowptr[i] = r;
        g_cursor[i] = r;
    }
    if (bid == NSB - 1 && tid == 0) g_rowptr[N_NODES] = base + total;
}

__global__ void scatter_kernel(const void* __restrict__ edge_raw) {
    int p = blockIdx.x * blockDim.x + threadIdx.x;      // edge pair index
    int e = p * 2;
    if (e >= N_EDGES) return;
    int s0, s1, d0, d1;
    if (g_is64) {
        longlong2 sv = ((const longlong2*)edge_raw)[p];
        longlong2 dv = ((const longlong2*)edge_raw)[N_EDGES / 2 + p];
        s0 = (int)sv.x; s1 = (int)sv.y; d0 = (int)dv.x; d1 = (int)dv.y;
    } else {
        int2 sv = ((const int2*)edge_raw)[p];
        int2 dv = ((const int2*)edge_raw)[N_EDGES / 2 + p];
        s0 = sv.x; s1 = sv.y; d0 = dv.x; d1 = dv.y;
    }
    if (s0 >= 0 && s0 < N_NODES && d0 >= 0 && d0 < N_NODES) {
        int pos = atomicAdd(&g_cursor[d0], 1);
        if (pos >= 0 && pos < N_EDGES) g_csr[pos] = s0;
    }
    if (e + 1 < N_EDGES && s1 >= 0 && s1 < N_NODES && d1 >= 0 && d1 < N_NODES) {
        int pos = atomicAdd(&g_cursor[d1], 1);
        if (pos >= 0 && pos < N_EDGES) g_csr[pos] = s1;
    }
}

// ---------------- gather fp16: h16 -> agg16 ----------------------------------
#define GMAX2(v) do { \
    m0 = __hmax2(m0, *(__half2*)&(v).x); m1 = __hmax2(m1, *(__half2*)&(v).y); \
    m2 = __hmax2(m2, *(__half2*)&(v).z); m3 = __hmax2(m3, *(__half2*)&(v).w); } while (0)

__global__ __launch_bounds__(GTPB) void gather16_kernel(
    const __half* __restrict__ h_in, __half* __restrict__ agg_out)
{
    int tid = threadIdx.x;
    int warp = tid >> 5, lane = tid & 31;
    int sub = lane >> 3, dl = lane & 7;

    int node = blockIdx.x * GNPB + warp * 4 + sub;
    if (node >= N_NODES) return;
    int start = g_rowptr[node];
    int end   = g_rowptr[node + 1];

    const __half neginf = __ushort_as_half((unsigned short)0xFC00);
    __half2 m0 = __half2half2(neginf), m1 = m0, m2 = m0, m3 = m0;

    int j = start;
    #pragma unroll 1
    for (; j + 8 <= end; j += 8) {
        int s0 = g_csr[j],     s1 = g_csr[j + 1];
        int s2 = g_csr[j + 2], s3 = g_csr[j + 3];
        int s4 = g_csr[j + 4], s5 = g_csr[j + 5];
        int s6 = g_csr[j + 6], s7 = g_csr[j + 7];
        uint4 v0 = *(const uint4*)(h_in + (size_t)s0 * D + dl * 8);
        uint4 v1 = *(const uint4*)(h_in + (size_t)s1 * D + dl * 8);
        uint4 v2 = *(const uint4*)(h_in + (size_t)s2 * D + dl * 8);
        uint4 v3 = *(const uint4*)(h_in + (size_t)s3 * D + dl * 8);
        uint4 v4 = *(const uint4*)(h_in + (size_t)s4 * D + dl * 8);
        uint4 v5 = *(const uint4*)(h_in + (size_t)s5 * D + dl * 8);
        uint4 v6 = *(const uint4*)(h_in + (size_t)s6 * D + dl * 8);
        uint4 v7 = *(const uint4*)(h_in + (size_t)s7 * D + dl * 8);
        GMAX2(v0); GMAX2(v1); GMAX2(v2); GMAX2(v3);
        GMAX2(v4); GMAX2(v5); GMAX2(v6); GMAX2(v7);
    }
    if (j + 4 <= end) {
        int s0 = g_csr[j],     s1 = g_csr[j + 1];
        int s2 = g_csr[j + 2], s3 = g_csr[j + 3];
        uint4 v0 = *(const uint4*)(h_in + (size_t)s0 * D + dl * 8);
        uint4 v1 = *(const uint4*)(h_in + (size_t)s1 * D + dl * 8);
        uint4 v2 = *(const uint4*)(h_in + (size_t)s2 * D + dl * 8);
        uint4 v3 = *(const uint4*)(h_in + (size_t)s3 * D + dl * 8);
        GMAX2(v0); GMAX2(v1); GMAX2(v2); GMAX2(v3);
        j += 4;
    }
    if (j + 2 <= end) {
        int s0 = g_csr[j], s1 = g_csr[j + 1];
        uint4 v0 = *(const uint4*)(h_in + (size_t)s0 * D + dl * 8);
        uint4 v1 = *(const uint4*)(h_in + (size_t)s1 * D + dl * 8);
        GMAX2(v0); GMAX2(v1);
        j += 2;
    }
    if (j < end) {
        int s0 = g_csr[j];
        uint4 v0 = *(const uint4*)(h_in + (size_t)s0 * D + dl * 8);
        GMAX2(v0);
    }
    if (start == end) {
        __half2 z = __half2half2(__ushort_as_half((unsigned short)0));
        m0 = z; m1 = z; m2 = z; m3 = z;
    }
    uint4 o;
    o.x = *(unsigned*)&m0; o.y = *(unsigned*)&m1;
    o.z = *(unsigned*)&m2; o.w = *(unsigned*)&m3;
    *(uint4*)(agg_out + (size_t)node * D + dl * 8) = o;
}

// ---------------- gemm (HMMA): out = relu([agg|h] @ [Wl;Wr] + bl) ------------
template <int OUT16>
__global__ __launch_bounds__(TPB) void gemm_kernel(
    const __half* __restrict__ ag, const __half* __restrict__ hh,
    void* __restrict__ outp,
    const float* __restrict__ Wl, const float* __restrict__ bl,
    const float* __restrict__ Wr, int layer)
{
    extern __shared__ __half smem16[];
    __half* sA = smem16;                  // [128][A_PITCH]: cols 0-63 agg, 64-127 h
    __half* sW = smem16 + SA_HALVES;      // [128][W_PITCH]: rows 0-63 Wl, 64-127 Wr
    float*  sB = (float*)(smem16 + SA_HALVES + SW_HALVES);

    int tid = threadIdx.x;
    int blockBase = blockIdx.x * NPB;

    // stage W (fp32 -> fp16)
    {
        const float4* wl4 = (const float4*)(Wl + layer * D * D);
        const float4* wr4 = (const float4*)(Wr + layer * D * D);
        #pragma unroll
        for (int i = tid; i < 2048; i += TPB) {
            int row = i >> 4, c = i & 15;
            float4 v = (row < 64) ? wl4[row * 16 + c] : wr4[(row - 64) * 16 + c];
            __half2 h0 = __floats2half2_rn(v.x, v.y);
            __half2 h1 = __floats2half2_rn(v.z, v.w);
            uint2 u;
            u.x = *(unsigned*)&h0; u.y = *(unsigned*)&h1;
            *(uint2*)(sW + row * W_PITCH + c * 4) = u;
        }
        if (tid < D) sB[tid] = bl[layer * D + tid];
    }
    // stage A = [agg | h]
    #pragma unroll
    for (int i = tid; i < NPB * 8; i += TPB) {
        int row = i >> 3, c = i & 7;
        int node = blockBase + row;
        uint4 va = make_uint4(0, 0, 0, 0), vh = va;
        if (node < N_NODES) {
            va = ((const uint4*)(ag + (size_t)node * D))[c];
            vh = ((const uint4*)(hh + (size_t)node * D))[c];
        }
        *(uint4*)(sA + row * A_PITCH + c * 8)      = va;
        *(uint4*)(sA + row * A_PITCH + 64 + c * 8) = vh;
    }
    __syncthreads();

    int warp = tid >> 5, lane = tid & 31;
    float acc[8][4];
    #pragma unroll
    for (int n = 0; n < 8; n++) {
        acc[n][0] = 0.f; acc[n][1] = 0.f; acc[n][2] = 0.f; acc[n][3] = 0.f;
    }

    unsigned aBase = s2u(sA) + ((warp * 16 + (lane & 15)) * A_PITCH + (lane >> 4) * 8) * 2;
    unsigned bBase = s2u(sW) + ((lane & 15) * W_PITCH) * 2;

    #pragma unroll
    for (int kk = 0; kk < 8; kk++) {
        unsigned a0, a1, a2, a3;
        ldmx4(a0, a1, a2, a3, aBase + kk * 16 * 2);
        unsigned brow = bBase + kk * 16 * W_PITCH * 2;
        #pragma unroll
        for (int n = 0; n < 8; n++) {
            unsigned b0, b1;
            ldmx2t(b0, b1, brow + n * 8 * 2);
            mma16816(acc[n], a0, a1, a2, a3, b0, b1);
        }
    }

    // epilogue: bias + relu
    int g = lane >> 2, t = lane & 3;
    if (OUT16) {
        __syncthreads();                  // reuse sA as sC
        #pragma unroll
        for (int n = 0; n < 8; n++) {
            int col = n * 8 + t * 2;
            float bx = sB[col], by = sB[col + 1];
            __half2 h01 = __floats2half2_rn(fmaxf(acc[n][0] + bx, 0.f),
                                            fmaxf(acc[n][1] + by, 0.f));
            __half2 h23 = __floats2half2_rn(fmaxf(acc[n][2] + bx, 0.f),
                                            fmaxf(acc[n][3] + by, 0.f));
            *(__half2*)(sA + (warp * 16 + g)     * A_PITCH + col) = h01;
            *(__half2*)(sA + (warp * 16 + g + 8) * A_PITCH + col) = h23;
        }
        __syncthreads();
        __half* o16 = (__half*)outp;
        #pragma unroll
        for (int i = tid; i < NPB * 8; i += TPB) {
            int row = i >> 3, c = i & 7;
            int node = blockBase + row;
            if (node < N_NODES)
                *(uint4*)(o16 + (size_t)node * D + c * 8) =
                    *(uint4*)(sA + row * A_PITCH + c * 8);
        }
    } else {
        float* o32 = (float*)outp;
        int row0 = blockBase + warp * 16 + g;
        int row1 = row0 + 8;
        #pragma unroll
        for (int n = 0; n < 8; n++) {
            int col = n * 8 + t * 2;
            float bx = sB[col], by = sB[col + 1];
            if (row0 < N_NODES) {
                float2 v = make_float2(fmaxf(acc[n][0] + bx, 0.f),
                                       fmaxf(acc[n][1] + by, 0.f));
                *(float2*)(o32 + (size_t)row0 * D + col) = v;
            }
            if (row1 < N_NODES) {
                float2 v = make_float2(fmaxf(acc[n][2] + bx, 0.f),
                                       fmaxf(acc[n][3] + by, 0.f));
                *(float2*)(o32 + (size_t)row1 * D + col) = v;
            }
        }
    }
}

// ---------------- launch -----------------------------------------------------
extern "C" void kernel_launch(void* const* d_in, const int* in_sizes, int n_in,
                              void* d_out, int out_size) {
    const float* x  = nullptr;
    const void*  edge = nullptr;
    const float* Wl = nullptr;
    const float* Wr = nullptr;
    const float* bl = nullptr;
    for (int i = 0; i < n_in; i++) {
        int sz = in_sizes[i];
        if (sz == N_NODES * D)            x    = (const float*)d_in[i];
        else if (sz == 2 * N_EDGES)       edge = d_in[i];
        else if (sz == N_LAYERS * D * D) { if (!Wl) Wl = (const float*)d_in[i];
                                           else     Wr = (const float*)d_in[i]; }
        else if (sz == N_LAYERS * D)      bl   = (const float*)d_in[i];
    }
    float* out = (float*)d_out;

    static int smem_set = 0;
    if (!smem_set) {
        cudaFuncSetAttribute(gemm_kernel<1>,
                             cudaFuncAttributeMaxDynamicSharedMemorySize, SMEM_BYTES);
        cudaFuncSetAttribute(gemm_kernel<0>,
                             cudaFuncAttributeMaxDynamicSharedMemorySize, SMEM_BYTES);
        smem_set = 1;
    }

    init_cvt_kernel<<<(N_NODES * D / 2 + 255) / 256, 256>>>(edge, x);
    histogram_kernel<<<(N_EDGES / 2 + 255) / 256, 256>>>(edge);
    scan_kernel<<<NSB, SBLK>>>();
    scatter_kernel<<<(N_EDGES / 2 + 255) / 256, 256>>>(edge);

    int gblocks = (N_NODES + GNPB - 1) / GNPB;
    int mblocks = (N_NODES + NPB - 1) / NPB;

    __half* x16 = nullptr; __half* h16a = nullptr; __half* h16b = nullptr;
    __half* agg16 = nullptr;
    cudaGetSymbolAddress((void**)&x16, g_x16);
    cudaGetSymbolAddress((void**)&h16a, g_h16a);
    cudaGetSymbolAddress((void**)&h16b, g_h16b);
    cudaGetSymbolAddress((void**)&agg16, g_agg16);

    // layer 1
    gather16_kernel<<<gblocks, GTPB>>>(x16, agg16);
    gemm_kernel<1><<<mblocks, TPB, SMEM_BYTES>>>(agg16, x16, h16a, Wl, bl, Wr, 0);
    // layer 2
    gather16_kernel<<<gblocks, GTPB>>>(h16a, agg16);
    gemm_kernel<1><<<mblocks, TPB, SMEM_BYTES>>>(agg16, h16a, h16b, Wl, bl, Wr, 1);
    // layer 3
    gather16_kernel<<<gblocks, GTPB>>>(h16b, agg16);
    gemm_kernel<1><<<mblocks, TPB, SMEM_BYTES>>>(agg16, h16b, h16a, Wl, bl, Wr, 2);
    // layer 4: fp32 out
    gather16_kernel<<<gblocks, GTPB>>>(h16a, agg16);
    gemm_kernel<0><<<mblocks, TPB, SMEM_BYTES>>>(agg16, h16a, out, Wl, bl, Wr, 3);
}

// round 13
// speedup vs baseline: 1.1412x; 1.0281x over previous
#include <cuda_runtime.h>
#include <cuda_fp16.h>
#include <math.h>

#define N_NODES 100000
#define N_EDGES 1250000
#define D 64
#define N_LAYERS 4

// ---- gemm kernel config ----
#define TPB 256                       // 8 warps, 1 M-tile (16 nodes) each
#define NPB 128                       // nodes per block
#define A_PITCH 136                   // halves; 272B row stride -> conflict-free LDSM
#define W_PITCH 72                    // halves; 144B row stride -> conflict-free LDSM
#define SA_HALVES (NPB * A_PITCH)     // 17408
#define SW_HALVES (128 * W_PITCH)     // 9216
#define SMEM_BYTES ((SA_HALVES + SW_HALVES) * 2 + D * 4)

// ---- gather kernel config ----
#define GTPB 256
#define GNPB 32

// ---- scan config ----
#define SBLK 1024
#define NSB ((N_NODES + SBLK - 1) / SBLK)   // 98 blocks <= 148 SMs: lookback safe

// ---- histogram grid (compile-time, used for fused conversion stride) ----
#define HBLOCKS ((N_EDGES / 2 + 255) / 256)   // 2442
#define HTHREADS (HBLOCKS * 256)              // 625152

// ---------------- scratch (static device globals; zero-init at load) ---------
__device__ __half g_x16[N_NODES * D];
__device__ __half g_h16a[N_NODES * D];
__device__ __half g_h16b[N_NODES * D];
__device__ __half g_agg16[N_NODES * D];
__device__ int    g_counts[N_NODES];          // invariant: all-zero at call entry
__device__ int    g_rowptr[N_NODES + 1];
__device__ int    g_cursor[N_NODES];
__device__ int    g_csr[N_EDGES];
__device__ unsigned long long g_bstat[NSB];   // lookback: flag<<32 | value
__device__ int    g_is64;

// ---------------- mma helpers ------------------------------------------------
__device__ __forceinline__ unsigned s2u(const void* p) {
    return (unsigned)__cvta_generic_to_shared(p);
}
__device__ __forceinline__ void ldmx4(unsigned& a0, unsigned& a1,
                                      unsigned& a2, unsigned& a3, unsigned addr) {
    asm volatile("ldmatrix.sync.aligned.m8n8.x4.shared.b16 {%0,%1,%2,%3}, [%4];"
                 : "=r"(a0), "=r"(a1), "=r"(a2), "=r"(a3) : "r"(addr));
}
__device__ __forceinline__ void ldmx2t(unsigned& b0, unsigned& b1, unsigned addr) {
    asm volatile("ldmatrix.sync.aligned.m8n8.x2.trans.shared.b16 {%0,%1}, [%2];"
                 : "=r"(b0), "=r"(b1) : "r"(addr));
}
__device__ __forceinline__ void mma16816(float* c, unsigned a0, unsigned a1,
                                         unsigned a2, unsigned a3,
                                         unsigned b0, unsigned b1) {
    asm volatile(
        "mma.sync.aligned.m16n8k16.row.col.f32.f16.f16.f32 "
        "{%0,%1,%2,%3}, {%4,%5,%6,%7}, {%8,%9}, {%0,%1,%2,%3};"
        : "+f"(c[0]), "+f"(c[1]), "+f"(c[2]), "+f"(c[3])
        : "r"(a0), "r"(a1), "r"(a2), "r"(a3), "r"(b0), "r"(b1));
}

// ---------------- init: dtype detect + zero lookback status (1 block) --------
__global__ void init_kernel(const void* __restrict__ edge_raw) {
    int i = threadIdx.x;
    if (i < NSB) g_bstat[i] = 0ull;
    if (i == 0) {
        const long long* e64 = (const long long*)edge_raw;
        int ok64 = 1;
        #pragma unroll 8
        for (int t = 0; t < 64; t++) {
            long long v = e64[t];
            if (v < 0 || v >= N_NODES) ok64 = 0;
        }
        g_is64 = ok64;
    }
}

// ---------------- histogram + fused x->fp16 conversion -----------------------
__global__ void histogram_kernel(const void* __restrict__ edge_raw,
                                 const float* __restrict__ x) {
    int p = blockIdx.x * blockDim.x + threadIdx.x;
    // fused conversion: each thread converts <=6 half2 (grid-strided)
    #pragma unroll 1
    for (int i = p; i < N_NODES * D / 2; i += HTHREADS) {
        float2 v = ((const float2*)x)[i];
        ((__half2*)g_x16)[i] = __floats2half2_rn(v.x, v.y);
    }
    int e = p * 2;
    if (e >= N_EDGES) return;
    int d0, d1;
    if (g_is64) {
        longlong2 v = ((const longlong2*)edge_raw)[N_EDGES / 2 + p];
        d0 = (int)v.x; d1 = (int)v.y;
    } else {
        int2 v = ((const int2*)edge_raw)[N_EDGES / 2 + p];
        d0 = v.x; d1 = v.y;
    }
    if (d0 >= 0 && d0 < N_NODES) atomicAdd(&g_counts[d0], 1);
    if (e + 1 < N_EDGES && d1 >= 0 && d1 < N_NODES) atomicAdd(&g_counts[d1], 1);
}

// single-pass decoupled-lookback exclusive scan (warp-parallel lookback).
// Also re-zeroes g_counts for the next call (module load guarantees first-call zero).
__global__ __launch_bounds__(SBLK) void scan_kernel() {
    __shared__ int wsum[32];
    __shared__ int sPrefix;
    int tid = threadIdx.x, lane = tid & 31, w = tid >> 5;
    int bid = blockIdx.x;
    int i = bid * SBLK + tid;
    int v = (i < N_NODES) ? g_counts[i] : 0;
    if (i < N_NODES) g_counts[i] = 0;         // restore invariant for next call

    int x = v;
    #pragma unroll
    for (int off = 1; off < 32; off <<= 1) {
        int y = __shfl_up_sync(0xffffffffu, x, off);
        if (lane >= off) x += y;
    }
    if (lane == 31) wsum[w] = x;
    __syncthreads();
    if (w == 0) {
        int s = wsum[lane];
        #pragma unroll
        for (int off = 1; off < 32; off <<= 1) {
            int y = __shfl_up_sync(0xffffffffu, s, off);
            if (lane >= off) s += y;
        }
        wsum[lane] = s;
    }
    __syncthreads();
    int incl = x + ((w > 0) ? wsum[w - 1] : 0);
    int total = wsum[31];                     // block aggregate

    if (w == 0) {                             // warp 0: publish + lookback
        int prefix = 0;
        if (bid > 0) {
            if (lane == 0)
                atomicExch(&g_bstat[bid], (1ull << 32) | (unsigned)total);
            int p = bid - 1;
            while (true) {
                int idx = p - lane;           // lane 0 = nearest predecessor
                unsigned long long s = (idx >= 0)
                    ? atomicAdd(&g_bstat[idx], 0ull) : (2ull << 32);
                unsigned flag = (unsigned)(s >> 32);
                if (!__all_sync(0xffffffffu, flag != 0u)) continue;  // retry window
                unsigned stopmask = __ballot_sync(0xffffffffu, flag == 2u);
                int firstStop = stopmask ? (__ffs(stopmask) - 1) : 32;
                int val = (idx >= 0 && lane <= firstStop) ? (int)(unsigned)s : 0;
                #pragma unroll
                for (int o = 16; o; o >>= 1)
                    val += __shfl_xor_sync(0xffffffffu, val, o);
                prefix += val;
                if (stopmask) break;
                p -= 32;
            }
        }
        if (lane == 0) {
            sPrefix = prefix;
            atomicExch(&g_bstat[bid], (2ull << 32) | (unsigned)(prefix + total));
        }
    }
    __syncthreads();
    int base = sPrefix;
    if (i < N_NODES) {
        int r = base + incl - v;
        g_rowptr[i] = r;
        g_cursor[i] = r;
    }
    if (bid == NSB - 1 && tid == 0) g_rowptr[N_NODES] = base + total;
}

__global__ void scatter_kernel(const void* __restrict__ edge_raw) {
    int p = blockIdx.x * blockDim.x + threadIdx.x;      // edge pair index
    int e = p * 2;
    if (e >= N_EDGES) return;
    int s0, s1, d0, d1;
    if (g_is64) {
        longlong2 sv = ((const longlong2*)edge_raw)[p];
        longlong2 dv = ((const longlong2*)edge_raw)[N_EDGES / 2 + p];
        s0 = (int)sv.x; s1 = (int)sv.y; d0 = (int)dv.x; d1 = (int)dv.y;
    } else {
        int2 sv = ((const int2*)edge_raw)[p];
        int2 dv = ((const int2*)edge_raw)[N_EDGES / 2 + p];
        s0 = sv.x; s1 = sv.y; d0 = dv.x; d1 = dv.y;
    }
    if (s0 >= 0 && s0 < N_NODES && d0 >= 0 && d0 < N_NODES) {
        int pos = atomicAdd(&g_cursor[d0], 1);
        if (pos >= 0 && pos < N_EDGES) g_csr[pos] = s0;
    }
    if (e + 1 < N_EDGES && s1 >= 0 && s1 < N_NODES && d1 >= 0 && d1 < N_NODES) {
        int pos = atomicAdd(&g_cursor[d1], 1);
        if (pos >= 0 && pos < N_EDGES) g_csr[pos] = s1;
    }
}

// ---------------- gather fp16: h16 -> agg16 ----------------------------------
#define GMAX2(v) do { \
    m0 = __hmax2(m0, *(__half2*)&(v).x); m1 = __hmax2(m1, *(__half2*)&(v).y); \
    m2 = __hmax2(m2, *(__half2*)&(v).z); m3 = __hmax2(m3, *(__half2*)&(v).w); } while (0)

__global__ __launch_bounds__(GTPB) void gather16_kernel(
    const __half* __restrict__ h_in, __half* __restrict__ agg_out)
{
    int tid = threadIdx.x;
    int warp = tid >> 5, lane = tid & 31;
    int sub = lane >> 3, dl = lane & 7;

    int node = blockIdx.x * GNPB + warp * 4 + sub;
    if (node >= N_NODES) return;
    int start = g_rowptr[node];
    int end   = g_rowptr[node + 1];

    const __half neginf = __ushort_as_half((unsigned short)0xFC00);
    __half2 m0 = __half2half2(neginf), m1 = m0, m2 = m0, m3 = m0;

    int j = start;
    #pragma unroll 1
    for (; j + 8 <= end; j += 8) {
        int s0 = g_csr[j],     s1 = g_csr[j + 1];
        int s2 = g_csr[j + 2], s3 = g_csr[j + 3];
        int s4 = g_csr[j + 4], s5 = g_csr[j + 5];
        int s6 = g_csr[j + 6], s7 = g_csr[j + 7];
        uint4 v0 = *(const uint4*)(h_in + (size_t)s0 * D + dl * 8);
        uint4 v1 = *(const uint4*)(h_in + (size_t)s1 * D + dl * 8);
        uint4 v2 = *(const uint4*)(h_in + (size_t)s2 * D + dl * 8);
        uint4 v3 = *(const uint4*)(h_in + (size_t)s3 * D + dl * 8);
        uint4 v4 = *(const uint4*)(h_in + (size_t)s4 * D + dl * 8);
        uint4 v5 = *(const uint4*)(h_in + (size_t)s5 * D + dl * 8);
        uint4 v6 = *(const uint4*)(h_in + (size_t)s6 * D + dl * 8);
        uint4 v7 = *(const uint4*)(h_in + (size_t)s7 * D + dl * 8);
        GMAX2(v0); GMAX2(v1); GMAX2(v2); GMAX2(v3);
        GMAX2(v4); GMAX2(v5); GMAX2(v6); GMAX2(v7);
    }
    if (j + 4 <= end) {
        int s0 = g_csr[j],     s1 = g_csr[j + 1];
        int s2 = g_csr[j + 2], s3 = g_csr[j + 3];
        uint4 v0 = *(const uint4*)(h_in + (size_t)s0 * D + dl * 8);
        uint4 v1 = *(const uint4*)(h_in + (size_t)s1 * D + dl * 8);
        uint4 v2 = *(const uint4*)(h_in + (size_t)s2 * D + dl * 8);
        uint4 v3 = *(const uint4*)(h_in + (size_t)s3 * D + dl * 8);
        GMAX2(v0); GMAX2(v1); GMAX2(v2); GMAX2(v3);
        j += 4;
    }
    if (j + 2 <= end) {
        int s0 = g_csr[j], s1 = g_csr[j + 1];
        uint4 v0 = *(const uint4*)(h_in + (size_t)s0 * D + dl * 8);
        uint4 v1 = *(const uint4*)(h_in + (size_t)s1 * D + dl * 8);
        GMAX2(v0); GMAX2(v1);
        j += 2;
    }
    if (j < end) {
        int s0 = g_csr[j];
        uint4 v0 = *(const uint4*)(h_in + (size_t)s0 * D + dl * 8);
        GMAX2(v0);
    }
    if (start == end) {
        __half2 z = __half2half2(__ushort_as_half((unsigned short)0));
        m0 = z; m1 = z; m2 = z; m3 = z;
    }
    uint4 o;
    o.x = *(unsigned*)&m0; o.y = *(unsigned*)&m1;
    o.z = *(unsigned*)&m2; o.w = *(unsigned*)&m3;
    *(uint4*)(agg_out + (size_t)node * D + dl * 8) = o;
}

// ---------------- gemm (HMMA): out = relu([agg|h] @ [Wl;Wr] + bl) ------------
template <int OUT16>
__global__ __launch_bounds__(TPB) void gemm_kernel(
    const __half* __restrict__ ag, const __half* __restrict__ hh,
    void* __restrict__ outp,
    const float* __restrict__ Wl, const float* __restrict__ bl,
    const float* __restrict__ Wr, int layer)
{
    extern __shared__ __half smem16[];
    __half* sA = smem16;                  // [128][A_PITCH]: cols 0-63 agg, 64-127 h
    __half* sW = smem16 + SA_HALVES;      // [128][W_PITCH]: rows 0-63 Wl, 64-127 Wr
    float*  sB = (float*)(smem16 + SA_HALVES + SW_HALVES);

    int tid = threadIdx.x;
    int blockBase = blockIdx.x * NPB;

    // stage W (fp32 -> fp16)
    {
        const float4* wl4 = (const float4*)(Wl + layer * D * D);
        const float4* wr4 = (const float4*)(Wr + layer * D * D);
        #pragma unroll
        for (int i = tid; i < 2048; i += TPB) {
            int row = i >> 4, c = i & 15;
            float4 v = (row < 64) ? wl4[row * 16 + c] : wr4[(row - 64) * 16 + c];
            __half2 h0 = __floats2half2_rn(v.x, v.y);
            __half2 h1 = __floats2half2_rn(v.z, v.w);
            uint2 u;
            u.x = *(unsigned*)&h0; u.y = *(unsigned*)&h1;
            *(uint2*)(sW + row * W_PITCH + c * 4) = u;
        }
        if (tid < D) sB[tid] = bl[layer * D + tid];
    }
    // stage A = [agg | h]
    #pragma unroll
    for (int i = tid; i < NPB * 8; i += TPB) {
        int row = i >> 3, c = i & 7;
        int node = blockBase + row;
        uint4 va = make_uint4(0, 0, 0, 0), vh = va;
        if (node < N_NODES) {
            va = ((const uint4*)(ag + (size_t)node * D))[c];
            vh = ((const uint4*)(hh + (size_t)node * D))[c];
        }
        *(uint4*)(sA + row * A_PITCH + c * 8)      = va;
        *(uint4*)(sA + row * A_PITCH + 64 + c * 8) = vh;
    }
    __syncthreads();

    int warp = tid >> 5, lane = tid & 31;
    float acc[8][4];
    #pragma unroll
    for (int n = 0; n < 8; n++) {
        acc[n][0] = 0.f; acc[n][1] = 0.f; acc[n][2] = 0.f; acc[n][3] = 0.f;
    }

    unsigned aBase = s2u(sA) + ((warp * 16 + (lane & 15)) * A_PITCH + (lane >> 4) * 8) * 2;
    unsigned bBase = s2u(sW) + ((lane & 15) * W_PITCH) * 2;

    #pragma unroll
    for (int kk = 0; kk < 8; kk++) {
        unsigned a0, a1, a2, a3;
        ldmx4(a0, a1, a2, a3, aBase + kk * 16 * 2);
        unsigned brow = bBase + kk * 16 * W_PITCH * 2;
        #pragma unroll
        for (int n = 0; n < 8; n++) {
            unsigned b0, b1;
            ldmx2t(b0, b1, brow + n * 8 * 2);
            mma16816(acc[n], a0, a1, a2, a3, b0, b1);
        }
    }

    // epilogue: bias + relu
    int g = lane >> 2, t = lane & 3;
    if (OUT16) {
        __syncthreads();                  // reuse sA as sC
        #pragma unroll
        for (int n = 0; n < 8; n++) {
            int col = n * 8 + t * 2;
            float bx = sB[col], by = sB[col + 1];
            __half2 h01 = __floats2half2_rn(fmaxf(acc[n][0] + bx, 0.f),
                                            fmaxf(acc[n][1] + by, 0.f));
            __half2 h23 = __floats2half2_rn(fmaxf(acc[n][2] + bx, 0.f),
                                            fmaxf(acc[n][3] + by, 0.f));
            *(__half2*)(sA + (warp * 16 + g)     * A_PITCH + col) = h01;
            *(__half2*)(sA + (warp * 16 + g + 8) * A_PITCH + col) = h23;
        }
        __syncthreads();
        __half* o16 = (__half*)outp;
        #pragma unroll
        for (int i = tid; i < NPB * 8; i += TPB) {
            int row = i >> 3, c = i & 7;
            int node = blockBase + row;
            if (node < N_NODES)
                *(uint4*)(o16 + (size_t)node * D + c * 8) =
                    *(uint4*)(sA + row * A_PITCH + c * 8);
        }
    } else {
        float* o32 = (float*)outp;
        int row0 = blockBase + warp * 16 + g;
        int row1 = row0 + 8;
        #pragma unroll
        for (int n = 0; n < 8; n++) {
            int col = n * 8 + t * 2;
            float bx = sB[col], by = sB[col + 1];
            if (row0 < N_NODES) {
                float2 v = make_float2(fmaxf(acc[n][0] + bx, 0.f),
                                       fmaxf(acc[n][1] + by, 0.f));
                *(float2*)(o32 + (size_t)row0 * D + col) = v;
            }
            if (row1 < N_NODES) {
                float2 v = make_float2(fmaxf(acc[n][2] + bx, 0.f),
                                       fmaxf(acc[n][3] + by, 0.f));
                *(float2*)(o32 + (size_t)row1 * D + col) = v;
            }
        }
    }
}

// ---------------- launch -----------------------------------------------------
extern "C" void kernel_launch(void* const* d_in, const int* in_sizes, int n_in,
                              void* d_out, int out_size) {
    const float* x  = nullptr;
    const void*  edge = nullptr;
    const float* Wl = nullptr;
    const float* Wr = nullptr;
    const float* bl = nullptr;
    for (int i = 0; i < n_in; i++) {
        int sz = in_sizes[i];
        if (sz == N_NODES * D)            x    = (const float*)d_in[i];
        else if (sz == 2 * N_EDGES)       edge = d_in[i];
        else if (sz == N_LAYERS * D * D) { if (!Wl) Wl = (const float*)d_in[i];
                                           else     Wr = (const float*)d_in[i]; }
        else if (sz == N_LAYERS * D)      bl   = (const float*)d_in[i];
    }
    float* out = (float*)d_out;

    static int smem_set = 0;
    if (!smem_set) {
        cudaFuncSetAttribute(gemm_kernel<1>,
                             cudaFuncAttributeMaxDynamicSharedMemorySize, SMEM_BYTES);
        cudaFuncSetAttribute(gemm_kernel<0>,
                             cudaFuncAttributeMaxDynamicSharedMemorySize, SMEM_BYTES);
        smem_set = 1;
    }

    init_kernel<<<1, 128>>>(edge);
    histogram_kernel<<<HBLOCKS, 256>>>(edge, x);
    scan_kernel<<<NSB, SBLK>>>();
    scatter_kernel<<<HBLOCKS, 256>>>(edge);

    int gblocks = (N_NODES + GNPB - 1) / GNPB;
    int mblocks = (N_NODES + NPB - 1) / NPB;

    __half* x16 = nullptr; __half* h16a = nullptr; __half* h16b = nullptr;
    __half* agg16 = nullptr;
    cudaGetSymbolAddress((void**)&x16, g_x16);
    cudaGetSymbolAddress((void**)&h16a, g_h16a);
    cudaGetSymbolAddress((void**)&h16b, g_h16b);
    cudaGetSymbolAddress((void**)&agg16, g_agg16);

    // layer 1
    gather16_kernel<<<gblocks, GTPB>>>(x16, agg16);
    gemm_kernel<1><<<mblocks, TPB, SMEM_BYTES>>>(agg16, x16, h16a, Wl, bl, Wr, 0);
    // layer 2
    gather16_kernel<<<gblocks, GTPB>>>(h16a, agg16);
    gemm_kernel<1><<<mblocks, TPB, SMEM_BYTES>>>(agg16, h16a, h16b, Wl, bl, Wr, 1);
    // layer 3
    gather16_kernel<<<gblocks, GTPB>>>(h16b, agg16);
    gemm_kernel<1><<<mblocks, TPB, SMEM_BYTES>>>(agg16, h16b, h16a, Wl, bl, Wr, 2);
    // layer 4: fp32 out
    gather16_kernel<<<gblocks, GTPB>>>(h16a, agg16);
    gemm_kernel<0><<<mblocks, TPB, SMEM_BYTES>>>(agg16, h16a, out, Wl, bl, Wr, 3);
}